// round 3
// baseline (speedup 1.0000x reference)
#include <cuda_runtime.h>
#include <math.h>

// Fused: energies[b*2048+s] = dot(hidden[b,:], enc[s,b,:]), then the warp that
// finishes the last row of batch b performs the softmax for that b in-place.
// Dot structure is identical to the 82.4us R1 kernel (1 warp/row, 8 independent
// float4 loads in flight, low regs -> high occupancy).

__device__ unsigned int g_cnt[64];   // static zero-init; self-resetting per launch

__global__ void __launch_bounds__(256) attn_fused_kernel(
    const float* __restrict__ hidden,   // [64, 1024]
    const float* __restrict__ enc,      // [2048, 64, 1024]
    float* __restrict__ out)            // [64, 2048] energies -> softmax in place
{
    int gwarp = (blockIdx.x * blockDim.x + threadIdx.x) >> 5;   // 0..131071
    int lane  = threadIdx.x & 31;

    int b = gwarp & 63;
    int s = gwarp >> 6;

    const float4* row = reinterpret_cast<const float4*>(enc + (size_t)gwarp * 1024);
    const float4* h   = reinterpret_cast<const float4*>(hidden + (size_t)b * 1024);

    float acc = 0.0f;
#pragma unroll
    for (int i = 0; i < 8; i++) {
        float4 e  = row[lane + i * 32];
        float4 hv = __ldg(&h[lane + i * 32]);
        acc = fmaf(e.x, hv.x, acc);
        acc = fmaf(e.y, hv.y, acc);
        acc = fmaf(e.z, hv.z, acc);
        acc = fmaf(e.w, hv.w, acc);
    }
#pragma unroll
    for (int o = 16; o; o >>= 1)
        acc += __shfl_xor_sync(0xffffffffu, acc, o);

    float* p = out + (size_t)b * 2048;

    // Publish energy, then arrive on per-b counter (threadfence-reduction pattern).
    int last = 0;
    if (lane == 0) {
        p[s] = acc;
        __threadfence();
        unsigned int old = atomicAdd(&g_cnt[b], 1u);
        last = (old == 2047u);
    }
    last = __shfl_sync(0xffffffffu, last, 0);
    if (!last) return;

    // This warp saw the final arrival for batch b: all 2048 energies are visible.
    if (lane == 0) g_cnt[b] = 0;     // reset for next graph replay

    const float4* pv = reinterpret_cast<const float4*>(p);

    // Pass 1: max (chunked, L2 reads, low register footprint)
    float m = -INFINITY;
    for (int i = lane; i < 512; i += 32) {
        float4 v = __ldcg(&pv[i]);
        m = fmaxf(m, fmaxf(fmaxf(v.x, v.y), fmaxf(v.z, v.w)));
    }
#pragma unroll
    for (int o = 16; o; o >>= 1)
        m = fmaxf(m, __shfl_xor_sync(0xffffffffu, m, o));

    // Pass 2: sum of exp
    float sum = 0.0f;
    for (int i = lane; i < 512; i += 32) {
        float4 v = __ldcg(&pv[i]);
        sum += __expf(v.x - m) + __expf(v.y - m) +
               __expf(v.z - m) + __expf(v.w - m);
    }
#pragma unroll
    for (int o = 16; o; o >>= 1)
        sum += __shfl_xor_sync(0xffffffffu, sum, o);
    float inv = 1.0f / sum;

    // Pass 3: write normalized probabilities
    float4* pw = reinterpret_cast<float4*>(p);
    for (int i = lane; i < 512; i += 32) {
        float4 v = __ldcg(&pv[i]);
        v.x = __expf(v.x - m) * inv;
        v.y = __expf(v.y - m) * inv;
        v.z = __expf(v.z - m) * inv;
        v.w = __expf(v.w - m) * inv;
        pw[i] = v;
    }
}

extern "C" void kernel_launch(void* const* d_in, const int* in_sizes, int n_in,
                              void* d_out, int out_size)
{
    const float* hidden = (const float*)d_in[0];   // [1, 64, 1024]
    const float* enc    = (const float*)d_in[1];   // [2048, 64, 1024]
    float* out          = (float*)d_out;           // [64, 1, 2048]

    // 131072 rows, 1 warp each, 8 warps (256 thr) per block -> 16384 blocks
    attn_fused_kernel<<<16384, 256>>>(hidden, enc, out);
}